// round 7
// baseline (speedup 1.0000x reference)
#include <cuda_runtime.h>
#include <cuda_fp16.h>
#include <cstdint>

// ---------------------------------------------------------------------------
// QuantLinearTensorWise: y[8192,16384] = x[8192,4096] @ (W*scale)^T + bias
// Portable tensor-core path (compute_103 target): ldmatrix + mma.sync m16n8k16.
// R6: 512 threads (4 warps/SMSP) x register double-buffered frag pipeline.
//     CTA 128x256x64, warp tile 64x32 (2M x 8N), 3-stage cp.async.
// ---------------------------------------------------------------------------

#define IN_F   4096
#define OUT_F  16384
#define NROWS  8192

#define BM 128
#define BN 256
#define BK 64
#define STAGES 3
#define THREADS 512
#define K_ITERS (IN_F / BK)        // 64
#define TILES_M (NROWS / BM)       // 64
#define TILES_N (OUT_F / BN)       // 64
#define GROUP_M 8

// padded smem rows: 64 halves data + 8 halves pad = 72 halves = 144 bytes
#define SROW 72
#define TILE_A_BYTES (BM * SROW * 2)               // 18432
#define TILE_B_BYTES (BN * SROW * 2)               // 36864
#define STAGE_BYTES (TILE_A_BYTES + TILE_B_BYTES)  // 55296
#define SMEM_TOTAL (STAGES * STAGE_BYTES)          // 165888

// fp16 scratch
__device__ __half g_xh[(size_t)NROWS * IN_F];
__device__ __half g_wh[(size_t)OUT_F * IN_F];

// ---------------------------------------------------------------------------
// Conversion kernels
// ---------------------------------------------------------------------------
__global__ void k_convert_x(const float4* __restrict__ x, int n4) {
    int i = blockIdx.x * blockDim.x + threadIdx.x;
    if (i < n4) {
        float4 v = x[i];
        __half2* o = reinterpret_cast<__half2*>(g_xh);
        o[2 * i]     = __floats2half2_rn(v.x, v.y);
        o[2 * i + 1] = __floats2half2_rn(v.z, v.w);
    }
}

__global__ void k_convert_w(const int4* __restrict__ w, int n4) {
    int i = blockIdx.x * blockDim.x + threadIdx.x;
    if (i < n4) {
        int4 v = w[i];
        __half2* o = reinterpret_cast<__half2*>(g_wh);
        o[2 * i]     = __halves2half2(__int2half_rn(v.x), __int2half_rn(v.y));
        o[2 * i + 1] = __halves2half2(__int2half_rn(v.z), __int2half_rn(v.w));
    }
}

// ---------------------------------------------------------------------------
// PTX helpers (portable sm_80+)
// ---------------------------------------------------------------------------
__device__ __forceinline__ uint32_t smem_u32(const void* p) {
    uint32_t a;
    asm("{ .reg .u64 t; cvta.to.shared.u64 t, %1; cvt.u32.u64 %0, t; }"
        : "=r"(a) : "l"(p));
    return a;
}

__device__ __forceinline__ void cp_async16(uint32_t dst, const void* src) {
    asm volatile("cp.async.cg.shared.global [%0], [%1], 16;"
                 :: "r"(dst), "l"(src) : "memory");
}

__device__ __forceinline__ void cp_commit() {
    asm volatile("cp.async.commit_group;" ::: "memory");
}

__device__ __forceinline__ void cp_wait1() {
    asm volatile("cp.async.wait_group 1;" ::: "memory");
}

__device__ __forceinline__ void ldmx4(uint32_t* r, uint32_t addr) {
    asm volatile("ldmatrix.sync.aligned.m8n8.x4.shared.b16 {%0,%1,%2,%3}, [%4];"
                 : "=r"(r[0]), "=r"(r[1]), "=r"(r[2]), "=r"(r[3]) : "r"(addr));
}

__device__ __forceinline__ void ldmx2(uint32_t* r, uint32_t addr) {
    asm volatile("ldmatrix.sync.aligned.m8n8.x2.shared.b16 {%0,%1}, [%2];"
                 : "=r"(r[0]), "=r"(r[1]) : "r"(addr));
}

__device__ __forceinline__ void mma16816(float* d, const uint32_t* a,
                                         const uint32_t* b) {
    asm volatile(
        "mma.sync.aligned.m16n8k16.row.col.f32.f16.f16.f32 "
        "{%0,%1,%2,%3}, {%4,%5,%6,%7}, {%8,%9}, {%0,%1,%2,%3};"
        : "+f"(d[0]), "+f"(d[1]), "+f"(d[2]), "+f"(d[3])
        : "r"(a[0]), "r"(a[1]), "r"(a[2]), "r"(a[3]), "r"(b[0]), "r"(b[1]));
}

// ---------------------------------------------------------------------------
// Stage load: A 128x64 + B 256x64 fp16, padded rows (8x16B chunks per row).
// A: 1024 chunks (2/thr); B: 2048 chunks (4/thr).
// ---------------------------------------------------------------------------
__device__ __forceinline__ void load_tile(uint32_t stage_base, int kt,
                                          int m0, int n0, int tid) {
    int k0 = kt * BK;
#pragma unroll
    for (int h = 0; h < 2; h++) {
        int idx = tid + h * THREADS;
        int row = idx >> 3, c = idx & 7;
        uint32_t off = (uint32_t)(row * (SROW * 2) + c * 16);
        cp_async16(stage_base + off,
                   g_xh + (size_t)(m0 + row) * IN_F + k0 + c * 8);
    }
    uint32_t bB = stage_base + TILE_A_BYTES;
#pragma unroll
    for (int h = 0; h < 4; h++) {
        int idx = tid + h * THREADS;
        int row = idx >> 3, c = idx & 7;
        uint32_t off = (uint32_t)(row * (SROW * 2) + c * 16);
        cp_async16(bB + off, g_wh + (size_t)(n0 + row) * IN_F + k0 + c * 8);
    }
}

// ---------------------------------------------------------------------------
// GEMM kernel: warp grid 2(M) x 8(N), warp tile 64x32, frag double-buffer
// ---------------------------------------------------------------------------
__global__ void __launch_bounds__(THREADS, 1)
gemm_hmma_kernel(const float* __restrict__ scale_p,
                 const float* __restrict__ bias,
                 float* __restrict__ out) {
    extern __shared__ char smem[];
    uint32_t sb = smem_u32(smem);
    int tid = threadIdx.x;
    int lane = tid & 31;
    int warp = tid >> 5;     // 0..15
    int wm = warp & 1;       // M dir: 64 rows
    int wn = warp >> 1;      // N dir: 0..7, 32 cols

    // tile raster with GROUP_M swizzle
    int pid = blockIdx.x;
    int per_group = GROUP_M * TILES_N;
    int g = pid / per_group;
    int rem = pid - g * per_group;
    int mt = g * GROUP_M + (rem % GROUP_M);
    int nt = rem / GROUP_M;
    int m0 = mt * BM, n0 = nt * BN;

    // ldmatrix lane address components (halves)
    int ar = (lane & 7) + ((lane >> 3) & 1) * 8;
    int ac = (lane >> 4) * 8;
    int bn_l = (lane & 7) + (lane >> 4) * 8;
    int bk_l = ((lane >> 3) & 1) * 8;

    // per-lane smem byte offsets (without stage/ks)
    uint32_t a_off[4], b_off[2];
#pragma unroll
    for (int mi = 0; mi < 4; mi++)
        a_off[mi] = (uint32_t)(((wm * 64 + mi * 16 + ar) * SROW + ac) * 2);
#pragma unroll
    for (int nj2 = 0; nj2 < 2; nj2++)
        b_off[nj2] = (uint32_t)(((wn * 32 + nj2 * 16 + bn_l) * SROW + bk_l) * 2);

    float acc[4][4][4];
#pragma unroll
    for (int i = 0; i < 4; i++)
#pragma unroll
        for (int j = 0; j < 4; j++)
#pragma unroll
            for (int r = 0; r < 4; r++) acc[i][j][r] = 0.0f;

#pragma unroll
    for (int s = 0; s < STAGES - 1; s++) {
        load_tile(sb + s * STAGE_BYTES, s, m0, n0, tid);
        cp_commit();
    }

    uint32_t a[2][4][4], b[2][2][4];

    for (int kt = 0; kt < K_ITERS; kt++) {
        cp_wait1();
        __syncthreads();

        uint32_t stg = sb + (kt % STAGES) * STAGE_BYTES;
        uint32_t aS = stg, bS = stg + TILE_A_BYTES;

        // prime ks=0 frags into buffer 0
#pragma unroll
        for (int mi = 0; mi < 4; mi++) ldmx4(a[0][mi], aS + a_off[mi]);
#pragma unroll
        for (int nj2 = 0; nj2 < 2; nj2++) ldmx4(b[0][nj2], bS + b_off[nj2]);

#pragma unroll
        for (int ks = 0; ks < 4; ks++) {
            int cur = ks & 1, nxt = cur ^ 1;

            if (ks == 0) {
                int nx = kt + STAGES - 1;
                if (nx < K_ITERS)
                    load_tile(sb + (nx % STAGES) * STAGE_BYTES, nx, m0, n0, tid);
                cp_commit();
            }

            // prefetch next ks frags before the HMMA block
            if (ks < 3) {
                uint32_t ko = (uint32_t)((ks + 1) * 16 * 2);
#pragma unroll
                for (int mi = 0; mi < 4; mi++)
                    ldmx4(a[nxt][mi], aS + a_off[mi] + ko);
#pragma unroll
                for (int nj2 = 0; nj2 < 2; nj2++)
                    ldmx4(b[nxt][nj2], bS + b_off[nj2] + ko);
            }

#pragma unroll
            for (int mi = 0; mi < 4; mi++) {
#pragma unroll
                for (int nj = 0; nj < 4; nj++)
                    mma16816(acc[mi][nj], a[cur][mi], &b[cur][nj >> 1][(nj & 1) * 2]);
            }
        }
    }

    // epilogue: y = acc*scale + bias
    float scl = *scale_p;
    int gid = lane >> 2, tig = lane & 3;
#pragma unroll
    for (int mi = 0; mi < 4; mi++) {
        int row0 = m0 + wm * 64 + mi * 16 + gid;
#pragma unroll
        for (int nj = 0; nj < 4; nj++) {
            int col = n0 + wn * 32 + nj * 8 + 2 * tig;
            float2 bb = *(const float2*)&bias[col];
            float2 v0, v1;
            v0.x = fmaf(acc[mi][nj][0], scl, bb.x);
            v0.y = fmaf(acc[mi][nj][1], scl, bb.y);
            v1.x = fmaf(acc[mi][nj][2], scl, bb.x);
            v1.y = fmaf(acc[mi][nj][3], scl, bb.y);
            *(float2*)&out[(size_t)row0 * OUT_F + col] = v0;
            *(float2*)&out[(size_t)(row0 + 8) * OUT_F + col] = v1;
        }
    }
}

// ---------------------------------------------------------------------------
// Launch
// ---------------------------------------------------------------------------
extern "C" void kernel_launch(void* const* d_in, const int* in_sizes, int n_in,
                              void* d_out, int out_size) {
    const float* x     = (const float*)d_in[0];
    const int*   w     = (const int*)d_in[1];
    const float* scale = (const float*)d_in[2];
    const float* bias  = (const float*)d_in[3];
    float* out = (float*)d_out;

    cudaFuncSetAttribute(gemm_hmma_kernel,
                         cudaFuncAttributeMaxDynamicSharedMemorySize, SMEM_TOTAL);

    int nx4 = NROWS * IN_F / 4;
    int nw4 = OUT_F * IN_F / 4;
    k_convert_x<<<nx4 / 256, 256>>>((const float4*)x, nx4);
    k_convert_w<<<nw4 / 256, 256>>>((const int4*)w, nw4);

    gemm_hmma_kernel<<<TILES_M * TILES_N, THREADS, SMEM_TOTAL>>>(scale, bias, out);
}

// round 8
// speedup vs baseline: 1.2402x; 1.2402x over previous
#include <cuda_runtime.h>
#include <cuda_fp16.h>
#include <cstdint>

// ---------------------------------------------------------------------------
// QuantLinearTensorWise: y[8192,16384] = x[8192,4096] @ (W*scale)^T + bias
// Portable tensor-core path (compute_103 target): ldmatrix + mma.sync m16n8k16.
// R7: R5 shape (256 thr, CTA 128x256x64, warp tile 64x64, 3-stage cp.async)
//     + CUTLASS-style CROSS-TILE frag pipelining: the register pipeline never
//     drains at k-tile boundaries; sync happens at ks==3 and next tile's ks=0
//     frags are prefetched immediately.
// ---------------------------------------------------------------------------

#define IN_F   4096
#define OUT_F  16384
#define NROWS  8192

#define BM 128
#define BN 256
#define BK 64
#define STAGES 3
#define THREADS 256
#define K_ITERS (IN_F / BK)        // 64
#define TILES_M (NROWS / BM)       // 64
#define TILES_N (OUT_F / BN)       // 64
#define GROUP_M 8

// padded smem rows: 64 halves data + 8 halves pad = 72 halves = 144 bytes
#define SROW 72
#define TILE_A_BYTES (BM * SROW * 2)               // 18432
#define TILE_B_BYTES (BN * SROW * 2)               // 36864
#define STAGE_BYTES (TILE_A_BYTES + TILE_B_BYTES)  // 55296
#define SMEM_TOTAL (STAGES * STAGE_BYTES)          // 165888

// fp16 scratch
__device__ __half g_xh[(size_t)NROWS * IN_F];
__device__ __half g_wh[(size_t)OUT_F * IN_F];

// ---------------------------------------------------------------------------
// Conversion kernels
// ---------------------------------------------------------------------------
__global__ void k_convert_x(const float4* __restrict__ x, int n4) {
    int i = blockIdx.x * blockDim.x + threadIdx.x;
    if (i < n4) {
        float4 v = x[i];
        __half2* o = reinterpret_cast<__half2*>(g_xh);
        o[2 * i]     = __floats2half2_rn(v.x, v.y);
        o[2 * i + 1] = __floats2half2_rn(v.z, v.w);
    }
}

__global__ void k_convert_w(const int4* __restrict__ w, int n4) {
    int i = blockIdx.x * blockDim.x + threadIdx.x;
    if (i < n4) {
        int4 v = w[i];
        __half2* o = reinterpret_cast<__half2*>(g_wh);
        o[2 * i]     = __halves2half2(__int2half_rn(v.x), __int2half_rn(v.y));
        o[2 * i + 1] = __halves2half2(__int2half_rn(v.z), __int2half_rn(v.w));
    }
}

// ---------------------------------------------------------------------------
// PTX helpers (portable sm_80+)
// ---------------------------------------------------------------------------
__device__ __forceinline__ uint32_t smem_u32(const void* p) {
    uint32_t a;
    asm("{ .reg .u64 t; cvta.to.shared.u64 t, %1; cvt.u32.u64 %0, t; }"
        : "=r"(a) : "l"(p));
    return a;
}

__device__ __forceinline__ void cp_async16(uint32_t dst, const void* src) {
    asm volatile("cp.async.cg.shared.global [%0], [%1], 16;"
                 :: "r"(dst), "l"(src) : "memory");
}

__device__ __forceinline__ void cp_commit() {
    asm volatile("cp.async.commit_group;" ::: "memory");
}

__device__ __forceinline__ void cp_wait1() {
    asm volatile("cp.async.wait_group 1;" ::: "memory");
}

__device__ __forceinline__ void ldmx4(uint32_t* r, uint32_t addr) {
    asm volatile("ldmatrix.sync.aligned.m8n8.x4.shared.b16 {%0,%1,%2,%3}, [%4];"
                 : "=r"(r[0]), "=r"(r[1]), "=r"(r[2]), "=r"(r[3]) : "r"(addr));
}

__device__ __forceinline__ void mma16816(float* d, const uint32_t* a,
                                         const uint32_t* b) {
    asm volatile(
        "mma.sync.aligned.m16n8k16.row.col.f32.f16.f16.f32 "
        "{%0,%1,%2,%3}, {%4,%5,%6,%7}, {%8,%9}, {%0,%1,%2,%3};"
        : "+f"(d[0]), "+f"(d[1]), "+f"(d[2]), "+f"(d[3])
        : "r"(a[0]), "r"(a[1]), "r"(a[2]), "r"(a[3]), "r"(b[0]), "r"(b[1]));
}

// ---------------------------------------------------------------------------
// Stage load: A 128x64 + B 256x64 fp16, padded rows (8x16B chunks per row).
// A: 1024 chunks (4/thr); B: 2048 chunks (8/thr).
// ---------------------------------------------------------------------------
__device__ __forceinline__ void load_tile(uint32_t stage_base, int kt,
                                          int m0, int n0, int tid) {
    int k0 = kt * BK;
#pragma unroll
    for (int h = 0; h < 4; h++) {
        int idx = tid + h * THREADS;
        int row = idx >> 3, c = idx & 7;
        uint32_t off = (uint32_t)(row * (SROW * 2) + c * 16);
        cp_async16(stage_base + off,
                   g_xh + (size_t)(m0 + row) * IN_F + k0 + c * 8);
    }
    uint32_t bB = stage_base + TILE_A_BYTES;
#pragma unroll
    for (int h = 0; h < 8; h++) {
        int idx = tid + h * THREADS;
        int row = idx >> 3, c = idx & 7;
        uint32_t off = (uint32_t)(row * (SROW * 2) + c * 16);
        cp_async16(bB + off, g_wh + (size_t)(n0 + row) * IN_F + k0 + c * 8);
    }
}

// ---------------------------------------------------------------------------
// GEMM kernel: warp grid 2(M) x 4(N), warp tile 64x64, cross-tile frag pipe
// ---------------------------------------------------------------------------
__global__ void __launch_bounds__(THREADS, 1)
gemm_hmma_kernel(const float* __restrict__ scale_p,
                 const float* __restrict__ bias,
                 float* __restrict__ out) {
    extern __shared__ char smem[];
    uint32_t sb = smem_u32(smem);
    int tid = threadIdx.x;
    int lane = tid & 31;
    int warp = tid >> 5;     // 0..7
    int wm = warp & 1;       // M dir: 64 rows
    int wn = warp >> 1;      // N dir: 0..3, 64 cols

    // tile raster with GROUP_M swizzle
    int pid = blockIdx.x;
    int per_group = GROUP_M * TILES_N;
    int g = pid / per_group;
    int rem = pid - g * per_group;
    int mt = g * GROUP_M + (rem % GROUP_M);
    int nt = rem / GROUP_M;
    int m0 = mt * BM, n0 = nt * BN;

    // ldmatrix lane address components (halves)
    int ar = (lane & 7) + ((lane >> 3) & 1) * 8;
    int ac = (lane >> 4) * 8;
    int bn_l = (lane & 7) + (lane >> 4) * 8;
    int bk_l = ((lane >> 3) & 1) * 8;

    // per-lane smem byte offsets (without stage/ks)
    uint32_t a_off[4], b_off[4];
#pragma unroll
    for (int mi = 0; mi < 4; mi++)
        a_off[mi] = (uint32_t)(((wm * 64 + mi * 16 + ar) * SROW + ac) * 2);
#pragma unroll
    for (int nj2 = 0; nj2 < 4; nj2++)
        b_off[nj2] = (uint32_t)(((wn * 64 + nj2 * 16 + bn_l) * SROW + bk_l) * 2);

    float acc[4][8][4];
#pragma unroll
    for (int i = 0; i < 4; i++)
#pragma unroll
        for (int j = 0; j < 8; j++)
#pragma unroll
            for (int r = 0; r < 4; r++) acc[i][j][r] = 0.0f;

#pragma unroll
    for (int s = 0; s < STAGES - 1; s++) {
        load_tile(sb + s * STAGE_BYTES, s, m0, n0, tid);
        cp_commit();
    }

    uint32_t a[2][4][4], b[2][4][4];

    // wait for stage 0, prime ks=0 frags (once, outside mainloop)
    cp_wait1();
    __syncthreads();
    uint32_t aS = sb, bS = sb + TILE_A_BYTES;
#pragma unroll
    for (int mi = 0; mi < 4; mi++) ldmx4(a[0][mi], aS + a_off[mi]);
#pragma unroll
    for (int nj2 = 0; nj2 < 4; nj2++) ldmx4(b[0][nj2], bS + b_off[nj2]);

    for (int kt = 0; kt < K_ITERS; kt++) {
#pragma unroll
        for (int ks = 0; ks < 4; ks++) {
            int cur = ks & 1, nxt = cur ^ 1;

            if (ks == 0) {
                // issue gmem->smem for stage kt+2 under this tile's compute
                int nx = kt + STAGES - 1;
                if (nx < K_ITERS)
                    load_tile(sb + (nx % STAGES) * STAGE_BYTES, nx, m0, n0, tid);
                cp_commit();
            }

            if (ks < 3) {
                // prefetch next ks frags from current stage
                uint32_t ko = (uint32_t)((ks + 1) * 16 * 2);
#pragma unroll
                for (int mi = 0; mi < 4; mi++)
                    ldmx4(a[nxt][mi], aS + a_off[mi] + ko);
#pragma unroll
                for (int nj2 = 0; nj2 < 4; nj2++)
                    ldmx4(b[nxt][nj2], bS + b_off[nj2] + ko);
            } else if (kt + 1 < K_ITERS) {
                // next stage is ready now: sync and prefetch ks=0 of next tile
                cp_wait1();
                __syncthreads();
                uint32_t stg = sb + ((kt + 1) % STAGES) * STAGE_BYTES;
                aS = stg;
                bS = stg + TILE_A_BYTES;
#pragma unroll
                for (int mi = 0; mi < 4; mi++)
                    ldmx4(a[nxt][mi], aS + a_off[mi]);
#pragma unroll
                for (int nj2 = 0; nj2 < 4; nj2++)
                    ldmx4(b[nxt][nj2], bS + b_off[nj2]);
            }

#pragma unroll
            for (int mi = 0; mi < 4; mi++) {
#pragma unroll
                for (int nj = 0; nj < 8; nj++)
                    mma16816(acc[mi][nj], a[cur][mi], &b[cur][nj >> 1][(nj & 1) * 2]);
            }
        }
    }

    // epilogue: y = acc*scale + bias
    float scl = *scale_p;
    int gid = lane >> 2, tig = lane & 3;
#pragma unroll
    for (int mi = 0; mi < 4; mi++) {
        int row0 = m0 + wm * 64 + mi * 16 + gid;
#pragma unroll
        for (int nj = 0; nj < 8; nj++) {
            int col = n0 + wn * 64 + nj * 8 + 2 * tig;
            float2 bb = *(const float2*)&bias[col];
            float2 v0, v1;
            v0.x = fmaf(acc[mi][nj][0], scl, bb.x);
            v0.y = fmaf(acc[mi][nj][1], scl, bb.y);
            v1.x = fmaf(acc[mi][nj][2], scl, bb.x);
            v1.y = fmaf(acc[mi][nj][3], scl, bb.y);
            *(float2*)&out[(size_t)row0 * OUT_F + col] = v0;
            *(float2*)&out[(size_t)(row0 + 8) * OUT_F + col] = v1;
        }
    }
}

// ---------------------------------------------------------------------------
// Launch
// ---------------------------------------------------------------------------
extern "C" void kernel_launch(void* const* d_in, const int* in_sizes, int n_in,
                              void* d_out, int out_size) {
    const float* x     = (const float*)d_in[0];
    const int*   w     = (const int*)d_in[1];
    const float* scale = (const float*)d_in[2];
    const float* bias  = (const float*)d_in[3];
    float* out = (float*)d_out;

    cudaFuncSetAttribute(gemm_hmma_kernel,
                         cudaFuncAttributeMaxDynamicSharedMemorySize, SMEM_TOTAL);

    int nx4 = NROWS * IN_F / 4;
    int nw4 = OUT_F * IN_F / 4;
    k_convert_x<<<nx4 / 256, 256>>>((const float4*)x, nx4);
    k_convert_w<<<nw4 / 256, 256>>>((const int4*)w, nw4);

    gemm_hmma_kernel<<<TILES_M * TILES_N, THREADS, SMEM_TOTAL>>>(scale, bias, out);
}

// round 9
// speedup vs baseline: 1.3220x; 1.0659x over previous
#include <cuda_runtime.h>
#include <cuda_fp16.h>
#include <cstdint>

// ---------------------------------------------------------------------------
// QuantLinearTensorWise: y[8192,16384] = x[8192,4096] @ (W*scale)^T + bias
// Portable tensor-core path (compute_103 target): ldmatrix + mma.sync m16n8k16.
// R8: R7 + STAGES=4 (deep cp.async buffer, wait_group 2) + stage loads spread
//     across ks-steps (A @ks0, B/2 @ks1, B/2+commit @ks2) to decongest LSU.
// ---------------------------------------------------------------------------

#define IN_F   4096
#define OUT_F  16384
#define NROWS  8192

#define BM 128
#define BN 256
#define BK 64
#define STAGES 4
#define THREADS 256
#define K_ITERS (IN_F / BK)        // 64
#define TILES_M (NROWS / BM)       // 64
#define TILES_N (OUT_F / BN)       // 64
#define GROUP_M 8

// padded smem rows: 64 halves data + 8 halves pad = 72 halves = 144 bytes
#define SROW 72
#define TILE_A_BYTES (BM * SROW * 2)               // 18432
#define TILE_B_BYTES (BN * SROW * 2)               // 36864
#define STAGE_BYTES (TILE_A_BYTES + TILE_B_BYTES)  // 55296
#define SMEM_TOTAL (STAGES * STAGE_BYTES)          // 221184

// fp16 scratch
__device__ __half g_xh[(size_t)NROWS * IN_F];
__device__ __half g_wh[(size_t)OUT_F * IN_F];

// ---------------------------------------------------------------------------
// Conversion kernels
// ---------------------------------------------------------------------------
__global__ void k_convert_x(const float4* __restrict__ x, int n4) {
    int i = blockIdx.x * blockDim.x + threadIdx.x;
    if (i < n4) {
        float4 v = x[i];
        __half2* o = reinterpret_cast<__half2*>(g_xh);
        o[2 * i]     = __floats2half2_rn(v.x, v.y);
        o[2 * i + 1] = __floats2half2_rn(v.z, v.w);
    }
}

__global__ void k_convert_w(const int4* __restrict__ w, int n4) {
    int i = blockIdx.x * blockDim.x + threadIdx.x;
    if (i < n4) {
        int4 v = w[i];
        __half2* o = reinterpret_cast<__half2*>(g_wh);
        o[2 * i]     = __halves2half2(__int2half_rn(v.x), __int2half_rn(v.y));
        o[2 * i + 1] = __halves2half2(__int2half_rn(v.z), __int2half_rn(v.w));
    }
}

// ---------------------------------------------------------------------------
// PTX helpers (portable sm_80+)
// ---------------------------------------------------------------------------
__device__ __forceinline__ uint32_t smem_u32(const void* p) {
    uint32_t a;
    asm("{ .reg .u64 t; cvta.to.shared.u64 t, %1; cvt.u32.u64 %0, t; }"
        : "=r"(a) : "l"(p));
    return a;
}

__device__ __forceinline__ void cp_async16(uint32_t dst, const void* src) {
    asm volatile("cp.async.cg.shared.global [%0], [%1], 16;"
                 :: "r"(dst), "l"(src) : "memory");
}

__device__ __forceinline__ void cp_commit() {
    asm volatile("cp.async.commit_group;" ::: "memory");
}

__device__ __forceinline__ void cp_wait2() {
    asm volatile("cp.async.wait_group 2;" ::: "memory");
}

__device__ __forceinline__ void ldmx4(uint32_t* r, uint32_t addr) {
    asm volatile("ldmatrix.sync.aligned.m8n8.x4.shared.b16 {%0,%1,%2,%3}, [%4];"
                 : "=r"(r[0]), "=r"(r[1]), "=r"(r[2]), "=r"(r[3]) : "r"(addr));
}

__device__ __forceinline__ void mma16816(float* d, const uint32_t* a,
                                         const uint32_t* b) {
    asm volatile(
        "mma.sync.aligned.m16n8k16.row.col.f32.f16.f16.f32 "
        "{%0,%1,%2,%3}, {%4,%5,%6,%7}, {%8,%9}, {%0,%1,%2,%3};"
        : "+f"(d[0]), "+f"(d[1]), "+f"(d[2]), "+f"(d[3])
        : "r"(a[0]), "r"(a[1]), "r"(a[2]), "r"(a[3]), "r"(b[0]), "r"(b[1]));
}

// ---------------------------------------------------------------------------
// Stage loads, split into three slices (A, B-half0, B-half1)
// ---------------------------------------------------------------------------
__device__ __forceinline__ void load_A(uint32_t stage_base, int kt,
                                       int m0, int tid) {
    int k0 = kt * BK;
#pragma unroll
    for (int h = 0; h < 4; h++) {
        int idx = tid + h * THREADS;
        int row = idx >> 3, c = idx & 7;
        uint32_t off = (uint32_t)(row * (SROW * 2) + c * 16);
        cp_async16(stage_base + off,
                   g_xh + (size_t)(m0 + row) * IN_F + k0 + c * 8);
    }
}

__device__ __forceinline__ void load_B(uint32_t stage_base, int kt,
                                       int n0, int tid, int half) {
    int k0 = kt * BK;
    uint32_t bB = stage_base + TILE_A_BYTES;
#pragma unroll
    for (int h = 0; h < 4; h++) {
        int idx = tid + (half * 4 + h) * THREADS;
        int row = idx >> 3, c = idx & 7;
        uint32_t off = (uint32_t)(row * (SROW * 2) + c * 16);
        cp_async16(bB + off, g_wh + (size_t)(n0 + row) * IN_F + k0 + c * 8);
    }
}

// ---------------------------------------------------------------------------
// GEMM kernel: warp grid 2(M) x 4(N), warp tile 64x64, cross-tile frag pipe
// ---------------------------------------------------------------------------
__global__ void __launch_bounds__(THREADS, 1)
gemm_hmma_kernel(const float* __restrict__ scale_p,
                 const float* __restrict__ bias,
                 float* __restrict__ out) {
    extern __shared__ char smem[];
    uint32_t sb = smem_u32(smem);
    int tid = threadIdx.x;
    int lane = tid & 31;
    int warp = tid >> 5;     // 0..7
    int wm = warp & 1;       // M dir: 64 rows
    int wn = warp >> 1;      // N dir: 0..3, 64 cols

    // tile raster with GROUP_M swizzle
    int pid = blockIdx.x;
    int per_group = GROUP_M * TILES_N;
    int g = pid / per_group;
    int rem = pid - g * per_group;
    int mt = g * GROUP_M + (rem % GROUP_M);
    int nt = rem / GROUP_M;
    int m0 = mt * BM, n0 = nt * BN;

    // ldmatrix lane address components (halves)
    int ar = (lane & 7) + ((lane >> 3) & 1) * 8;
    int ac = (lane >> 4) * 8;
    int bn_l = (lane & 7) + (lane >> 4) * 8;
    int bk_l = ((lane >> 3) & 1) * 8;

    // per-lane smem byte offsets (without stage/ks)
    uint32_t a_off[4], b_off[4];
#pragma unroll
    for (int mi = 0; mi < 4; mi++)
        a_off[mi] = (uint32_t)(((wm * 64 + mi * 16 + ar) * SROW + ac) * 2);
#pragma unroll
    for (int nj2 = 0; nj2 < 4; nj2++)
        b_off[nj2] = (uint32_t)(((wn * 64 + nj2 * 16 + bn_l) * SROW + bk_l) * 2);

    float acc[4][8][4];
#pragma unroll
    for (int i = 0; i < 4; i++)
#pragma unroll
        for (int j = 0; j < 8; j++)
#pragma unroll
            for (int r = 0; r < 4; r++) acc[i][j][r] = 0.0f;

    // prologue: fill STAGES-1 = 3 stages, one commit group each
#pragma unroll
    for (int s = 0; s < STAGES - 1; s++) {
        uint32_t st = sb + s * STAGE_BYTES;
        load_A(st, s, m0, tid);
        load_B(st, s, n0, tid, 0);
        load_B(st, s, n0, tid, 1);
        cp_commit();
    }

    uint32_t a[2][4][4], b[2][4][4];

    // wait for stage 0 (all but last 2 groups retired), prime ks=0 frags
    cp_wait2();
    __syncthreads();
    uint32_t aS = sb, bS = sb + TILE_A_BYTES;
#pragma unroll
    for (int mi = 0; mi < 4; mi++) ldmx4(a[0][mi], aS + a_off[mi]);
#pragma unroll
    for (int nj2 = 0; nj2 < 4; nj2++) ldmx4(b[0][nj2], bS + b_off[nj2]);

    for (int kt = 0; kt < K_ITERS; kt++) {
        int nx = kt + STAGES - 1;
        uint32_t nstg = sb + (nx % STAGES) * STAGE_BYTES;

#pragma unroll
        for (int ks = 0; ks < 4; ks++) {
            int cur = ks & 1, nxt = cur ^ 1;

            // spread gmem->smem issuance: A @ks0, B half @ks1, B half @ks2
            if (ks == 0) {
                if (nx < K_ITERS) load_A(nstg, nx, m0, tid);
            } else if (ks == 1) {
                if (nx < K_ITERS) load_B(nstg, nx, n0, tid, 0);
            } else if (ks == 2) {
                if (nx < K_ITERS) load_B(nstg, nx, n0, tid, 1);
                cp_commit();   // exactly one group per tile (may be empty)
            }

            if (ks < 3) {
                // prefetch next ks frags from current stage
                uint32_t ko = (uint32_t)((ks + 1) * 16 * 2);
#pragma unroll
                for (int mi = 0; mi < 4; mi++)
                    ldmx4(a[nxt][mi], aS + a_off[mi] + ko);
#pragma unroll
                for (int nj2 = 0; nj2 < 4; nj2++)
                    ldmx4(b[nxt][nj2], bS + b_off[nj2] + ko);
            } else if (kt + 1 < K_ITERS) {
                // next stage ready long ago (3-deep buffer): cheap wait
                cp_wait2();
                __syncthreads();
                uint32_t stg = sb + ((kt + 1) % STAGES) * STAGE_BYTES;
                aS = stg;
                bS = stg + TILE_A_BYTES;
#pragma unroll
                for (int mi = 0; mi < 4; mi++)
                    ldmx4(a[nxt][mi], aS + a_off[mi]);
#pragma unroll
                for (int nj2 = 0; nj2 < 4; nj2++)
                    ldmx4(b[nxt][nj2], bS + b_off[nj2]);
            }

#pragma unroll
            for (int mi = 0; mi < 4; mi++) {
#pragma unroll
                for (int nj = 0; nj < 8; nj++)
                    mma16816(acc[mi][nj], a[cur][mi], &b[cur][nj >> 1][(nj & 1) * 2]);
            }
        }
    }

    // epilogue: y = acc*scale + bias
    float scl = *scale_p;
    int gid = lane >> 2, tig = lane & 3;
#pragma unroll
    for (int mi = 0; mi < 4; mi++) {
        int row0 = m0 + wm * 64 + mi * 16 + gid;
#pragma unroll
        for (int nj = 0; nj < 8; nj++) {
            int col = n0 + wn * 64 + nj * 8 + 2 * tig;
            float2 bb = *(const float2*)&bias[col];
            float2 v0, v1;
            v0.x = fmaf(acc[mi][nj][0], scl, bb.x);
            v0.y = fmaf(acc[mi][nj][1], scl, bb.y);
            v1.x = fmaf(acc[mi][nj][2], scl, bb.x);
            v1.y = fmaf(acc[mi][nj][3], scl, bb.y);
            *(float2*)&out[(size_t)row0 * OUT_F + col] = v0;
            *(float2*)&out[(size_t)(row0 + 8) * OUT_F + col] = v1;
        }
    }
}

// ---------------------------------------------------------------------------
// Launch
// ---------------------------------------------------------------------------
extern "C" void kernel_launch(void* const* d_in, const int* in_sizes, int n_in,
                              void* d_out, int out_size) {
    const float* x     = (const float*)d_in[0];
    const int*   w     = (const int*)d_in[1];
    const float* scale = (const float*)d_in[2];
    const float* bias  = (const float*)d_in[3];
    float* out = (float*)d_out;

    cudaFuncSetAttribute(gemm_hmma_kernel,
                         cudaFuncAttributeMaxDynamicSharedMemorySize, SMEM_TOTAL);

    int nx4 = NROWS * IN_F / 4;
    int nw4 = OUT_F * IN_F / 4;
    k_convert_x<<<nx4 / 256, 256>>>((const float4*)x, nx4);
    k_convert_w<<<nw4 / 256, 256>>>((const int4*)w, nw4);

    gemm_hmma_kernel<<<TILES_M * TILES_N, THREADS, SMEM_TOTAL>>>(scale, bias, out);
}